// round 2
// baseline (speedup 1.0000x reference)
#include <cuda_runtime.h>
#include <cuda_bf16.h>
#include <math.h>

#define BB   4
#define CIN  1024
#define CO   256
#define NN   16384          // H*W
#define NB   (BB*NN)        // 65536
#define CQ   32
#define FN   16384.0f

// ---------------- scratch (device globals; no allocations allowed) ----------
__device__ float g_feat[BB*CO*NN];     // conv out -> BN'd feat (67MB)
__device__ float g_Q[BB*CQ*NN];        // 8.4MB
__device__ float g_K[BB*CQ*NN];        // 8.4MB
__device__ float g_V[BB*CO*NN];        // 67MB
__device__ float g_scale[CO];
__device__ float g_shift[CO];
__device__ float g_Ksum[BB*CQ];
__device__ float g_Vsum[BB*CO];
__device__ float g_matrix[BB*CQ*CO];   // [b][q][c]

// ---------------- 1: 1x1 conv as GEMM: feat[b,o,n] = sum_c w[o,c]*fcat[b,c,n]
// M=256 (o), N=65536 (m=b*NN+n), K=1024 (c). 64x64x16 tiles, 256 thr, 4x4/thr.
__global__ __launch_bounds__(256) void conv_gemm(
    const float* __restrict__ s5, const float* __restrict__ s4,
    const float* __restrict__ s3, const float* __restrict__ s2,
    const float* __restrict__ w)
{
    __shared__ float As[16][64];
    __shared__ float Bs[16][64];
    const int tid = threadIdx.x;
    const int tx = tid & 15, ty = tid >> 4;
    const int m0 = blockIdx.x * 64;
    const int o0 = blockIdx.y * 64;
    const int b  = m0 >> 14;          // NN=16384, tiles never cross batch
    const int n0 = m0 & (NN - 1);

    float acc[4][4] = {};
    for (int k0 = 0; k0 < CIN; k0 += 16) {
        // source tensor constant within a k-tile (256 % 16 == 0)
        const float* src = (k0 < 256) ? s5 : (k0 < 512) ? s4 : (k0 < 768) ? s3 : s2;
        const int crem0 = k0 & 255;
        #pragma unroll
        for (int l = 0; l < 4; l++) {           // A: 64(o) x 16(k)
            int idx = tid + l * 256;
            int k = idx & 15, o = idx >> 4;
            As[k][o] = w[(o0 + o) * CIN + k0 + k];
        }
        #pragma unroll
        for (int l = 0; l < 4; l++) {           // B: 16(k) x 64(m)
            int idx = tid + l * 256;
            int mm = idx & 63, k = idx >> 6;
            Bs[k][mm] = src[((b << 8) + crem0 + k) * NN + n0 + mm];
        }
        __syncthreads();
        #pragma unroll
        for (int kk = 0; kk < 16; kk++) {
            float4 a  = *(const float4*)&As[kk][ty * 4];
            float4 bv = *(const float4*)&Bs[kk][tx * 4];
            acc[0][0] += a.x*bv.x; acc[0][1] += a.x*bv.y; acc[0][2] += a.x*bv.z; acc[0][3] += a.x*bv.w;
            acc[1][0] += a.y*bv.x; acc[1][1] += a.y*bv.y; acc[1][2] += a.y*bv.z; acc[1][3] += a.y*bv.w;
            acc[2][0] += a.z*bv.x; acc[2][1] += a.z*bv.y; acc[2][2] += a.z*bv.z; acc[2][3] += a.z*bv.w;
            acc[3][0] += a.w*bv.x; acc[3][1] += a.w*bv.y; acc[3][2] += a.w*bv.z; acc[3][3] += a.w*bv.w;
        }
        __syncthreads();
    }
    #pragma unroll
    for (int i = 0; i < 4; i++) {
        int o = o0 + ty * 4 + i;
        float4 v = make_float4(acc[i][0], acc[i][1], acc[i][2], acc[i][3]);
        *(float4*)&g_feat[(b * CO + o) * NN + n0 + tx * 4] = v;
    }
}

// ---------------- 2: per-channel BN stats -> scale/shift -------------------
__global__ __launch_bounds__(256) void bn_stats(
    const float* __restrict__ bn_gamma, const float* __restrict__ bn_beta)
{
    const int o = blockIdx.x;
    const int t = threadIdx.x;
    float s = 0.f, ss = 0.f;
    for (int b = 0; b < BB; b++) {
        const float* p = g_feat + (b * CO + o) * NN;
        for (int n = t; n < NN; n += 256) { float v = p[n]; s += v; ss += v * v; }
    }
    __shared__ float sh[256], sh2[256];
    sh[t] = s; sh2[t] = ss; __syncthreads();
    for (int st = 128; st > 0; st >>= 1) {
        if (t < st) { sh[t] += sh[t + st]; sh2[t] += sh2[t + st]; }
        __syncthreads();
    }
    if (t == 0) {
        const float inv = 1.0f / (float)(BB * NN);
        float mean = sh[0] * inv;
        float var  = sh2[0] * inv - mean * mean;
        float sc   = bn_gamma[o] * rsqrtf(var + 1e-5f);
        g_scale[o] = sc;
        g_shift[o] = bn_beta[o] - mean * sc;
    }
}

// ---------------- 3: BN + ReLU in place (float4) ---------------------------
__global__ __launch_bounds__(256) void bn_apply()
{
    int idx4 = blockIdx.x * 256 + threadIdx.x;       // BB*CO*NN/4 elems
    int o = (idx4 >> 12) & 255;                       // (idx4*4)>>14 & 255
    float sc = g_scale[o], sh = g_shift[o];
    float4 v = *(float4*)&g_feat[idx4 * 4];
    v.x = fmaxf(v.x * sc + sh, 0.f);
    v.y = fmaxf(v.y * sc + sh, 0.f);
    v.z = fmaxf(v.z * sc + sh, 0.f);
    v.w = fmaxf(v.w * sc + sh, 0.f);
    *(float4*)&g_feat[idx4 * 4] = v;
}

// ---------------- 4: fused QKV GEMM: M=320 rows over feat ------------------
__global__ __launch_bounds__(256) void qkv_gemm(
    const float* __restrict__ wq, const float* __restrict__ bq,
    const float* __restrict__ wk, const float* __restrict__ bk,
    const float* __restrict__ wv, const float* __restrict__ bv)
{
    __shared__ float As[16][64];
    __shared__ float Bs[16][64];
    const int tid = threadIdx.x;
    const int tx = tid & 15, ty = tid >> 4;
    const int m0 = blockIdx.x * 64;
    const int r0 = blockIdx.y * 64;      // 0..256
    const int b  = m0 >> 14;
    const int n0 = m0 & (NN - 1);

    float acc[4][4] = {};
    for (int k0 = 0; k0 < CO; k0 += 16) {
        #pragma unroll
        for (int l = 0; l < 4; l++) {
            int idx = tid + l * 256;
            int k = idx & 15, o = idx >> 4;
            int r = r0 + o;
            const float* wrow = (r < 32) ? (wq + r * CO)
                              : (r < 64) ? (wk + (r - 32) * CO)
                                         : (wv + (r - 64) * CO);
            As[k][o] = wrow[k0 + k];
        }
        #pragma unroll
        for (int l = 0; l < 4; l++) {
            int idx = tid + l * 256;
            int mm = idx & 63, k = idx >> 6;
            Bs[k][mm] = g_feat[(b * CO + k0 + k) * NN + n0 + mm];
        }
        __syncthreads();
        #pragma unroll
        for (int kk = 0; kk < 16; kk++) {
            float4 a  = *(const float4*)&As[kk][ty * 4];
            float4 bv4 = *(const float4*)&Bs[kk][tx * 4];
            acc[0][0] += a.x*bv4.x; acc[0][1] += a.x*bv4.y; acc[0][2] += a.x*bv4.z; acc[0][3] += a.x*bv4.w;
            acc[1][0] += a.y*bv4.x; acc[1][1] += a.y*bv4.y; acc[1][2] += a.y*bv4.z; acc[1][3] += a.y*bv4.w;
            acc[2][0] += a.z*bv4.x; acc[2][1] += a.z*bv4.y; acc[2][2] += a.z*bv4.z; acc[2][3] += a.z*bv4.w;
            acc[3][0] += a.w*bv4.x; acc[3][1] += a.w*bv4.y; acc[3][2] += a.w*bv4.z; acc[3][3] += a.w*bv4.w;
        }
        __syncthreads();
    }
    #pragma unroll
    for (int i = 0; i < 4; i++) {
        int r = r0 + ty * 4 + i;
        float bias; float* dst;
        if (r < 32)      { bias = bq[r];      dst = &g_Q[(b * CQ + r) * NN]; }
        else if (r < 64) { bias = bk[r - 32]; dst = &g_K[(b * CQ + r - 32) * NN]; }
        else             { bias = bv[r - 64]; dst = &g_V[(b * CO + r - 64) * NN]; }
        float4 v = make_float4(acc[i][0] + bias, acc[i][1] + bias,
                               acc[i][2] + bias, acc[i][3] + bias);
        *(float4*)&dst[n0 + tx * 4] = v;
    }
}

// ---------------- 5: L2-normalize Q and K over channel dim (per column) ----
__global__ __launch_bounds__(256) void l2norm_qk()
{
    int col = blockIdx.x * 256 + threadIdx.x;    // 0..NB-1
    int b = col >> 14, n = col & (NN - 1);
    {
        float* p = g_Q + b * CQ * NN + n;
        float v[CQ]; float s = 0.f;
        #pragma unroll
        for (int q = 0; q < CQ; q++) { v[q] = p[q * NN]; s += v[q] * v[q]; }
        float r = 1.f / fmaxf(sqrtf(s), 1e-6f);
        #pragma unroll
        for (int q = 0; q < CQ; q++) p[q * NN] = v[q] * r;
    }
    {
        float* p = g_K + b * CQ * NN + n;
        float v[CQ]; float s = 0.f;
        #pragma unroll
        for (int q = 0; q < CQ; q++) { v[q] = p[q * NN]; s += v[q] * v[q]; }
        float r = 1.f / fmaxf(sqrtf(s), 1e-6f);
        #pragma unroll
        for (int q = 0; q < CQ; q++) p[q * NN] = v[q] * r;
    }
}

// ---------------- 6: row sums: Ksum[b,q], Vsum[b,c] ------------------------
__global__ __launch_bounds__(256) void row_sums()
{
    const int id = blockIdx.x;            // BB*(CQ+CO)
    const int b = id / (CQ + CO);
    const int r = id % (CQ + CO);
    const float* p; float* dst;
    if (r < CQ) { p = g_K + (b * CQ + r) * NN;        dst = &g_Ksum[b * CQ + r]; }
    else        { p = g_V + (b * CO + (r - CQ)) * NN; dst = &g_Vsum[b * CO + r - CQ]; }
    const int t = threadIdx.x;
    float s = 0.f;
    for (int n = t; n < NN; n += 256) s += p[n];
    __shared__ float sh[256];
    sh[t] = s; __syncthreads();
    for (int st = 128; st > 0; st >>= 1) {
        if (t < st) sh[t] += sh[t + st];
        __syncthreads();
    }
    if (t == 0) *dst = sh[0];
}

// ---------------- 7: matrix[b,q,c] = sum_n Kn[b,q,n] * V[b,c,n] ------------
__global__ __launch_bounds__(256) void kv_matrix()
{
    const int b = blockIdx.x >> 8;
    const int c = blockIdx.x & 255;
    const float* __restrict__ V  = g_V + (b * CO + c) * NN;
    const float* __restrict__ Kb = g_K + b * CQ * NN;
    const int t = threadIdx.x;
    float acc[CQ] = {};
    for (int n = t; n < NN; n += 256) {
        float v = V[n];
        #pragma unroll
        for (int q = 0; q < CQ; q++) acc[q] += Kb[q * NN + n] * v;
    }
    const int lane = t & 31, wid = t >> 5;
    __shared__ float red[8][CQ];
    #pragma unroll
    for (int q = 0; q < CQ; q++) {
        float v = acc[q];
        #pragma unroll
        for (int o = 16; o > 0; o >>= 1) v += __shfl_down_sync(0xffffffffu, v, o);
        if (lane == 0) red[wid][q] = v;
    }
    __syncthreads();
    if (t < CQ) {
        float s = 0.f;
        #pragma unroll
        for (int w8 = 0; w8 < 8; w8++) s += red[w8][t];
        g_matrix[(b * CQ + t) * CO + c] = s;
    }
}

// ---------------- 8: final: out = feat + nan2num(gamma*(Vsum + Qn.M)*tailor)
__global__ __launch_bounds__(256) void final_out(
    const float* __restrict__ gamma_p, float* __restrict__ out)
{
    const int b  = blockIdx.x >> 8;         // grid = BB * (NN/64)
    const int n0 = (blockIdx.x & 255) * 64;
    __shared__ float qsh[CQ][64];           // Qn tile
    __shared__ float msh[CQ][CO];           // matrix[b]
    __shared__ float vsum_sh[CO];
    __shared__ float ksum_sh[CQ];
    __shared__ float tail[64];
    const int t = threadIdx.x;

    #pragma unroll
    for (int l = 0; l < 32; l++) {          // 32*256 matrix elems
        int idx = t + l * 256;
        msh[idx >> 8][idx & 255] = g_matrix[b * CQ * CO + idx];
    }
    if (t < CO) vsum_sh[t] = g_Vsum[b * CO + t];
    if (t < CQ) ksum_sh[t] = g_Ksum[b * CQ + t];
    #pragma unroll
    for (int l = 0; l < 8; l++) {           // 32*64 Qn elems
        int idx = t + l * 256;
        int q = idx >> 6, n = idx & 63;
        qsh[q][n] = g_Q[(b * CQ + q) * NN + n0 + n];
    }
    __syncthreads();
    if (t < 64) {
        float e = 0.f;
        #pragma unroll
        for (int q = 0; q < CQ; q++) e += qsh[q][t] * ksum_sh[q];
        tail[t] = 1.f / fmaxf(FN + e, 1e-6f);
    }
    __syncthreads();

    const float gam = gamma_p[0];
    const int n = t & 63;
    const int cbase = t >> 6;               // 0..3
    float qreg[CQ];
    #pragma unroll
    for (int q = 0; q < CQ; q++) qreg[q] = qsh[q][n];
    const float tl = tail[n];

    #pragma unroll 4
    for (int i = 0; i < 64; i++) {
        int c = cbase + i * 4;
        float s = vsum_sh[c];
        #pragma unroll
        for (int q = 0; q < CQ; q++) s += qreg[q] * msh[q][c];
        float v = gam * s * tl;
        if (isnan(v)) v = 0.f;
        else if (isinf(v)) v = (v > 0.f) ? 1.f : -1.f;
        int gi = (b * CO + c) * NN + n0 + n;
        out[gi] = v + g_feat[gi];
    }
}

// ---------------------------------------------------------------------------
extern "C" void kernel_launch(void* const* d_in, const int* in_sizes, int n_in,
                              void* d_out, int out_size)
{
    const float* s5       = (const float*)d_in[0];
    const float* s4       = (const float*)d_in[1];
    const float* s3       = (const float*)d_in[2];
    const float* s2       = (const float*)d_in[3];
    const float* w_conv   = (const float*)d_in[4];
    const float* bn_gamma = (const float*)d_in[5];
    const float* bn_beta  = (const float*)d_in[6];
    const float* wq       = (const float*)d_in[7];
    const float* bq       = (const float*)d_in[8];
    const float* wk       = (const float*)d_in[9];
    const float* bk       = (const float*)d_in[10];
    const float* wv       = (const float*)d_in[11];
    const float* bv       = (const float*)d_in[12];
    const float* gamma    = (const float*)d_in[13];
    float* out = (float*)d_out;

    conv_gemm<<<dim3(NB / 64, CO / 64), 256>>>(s5, s4, s3, s2, w_conv);
    bn_stats<<<CO, 256>>>(bn_gamma, bn_beta);
    bn_apply<<<(BB * CO * NN / 4) / 256, 256>>>();
    qkv_gemm<<<dim3(NB / 64, 5), 256>>>(wq, bq, wk, bk, wv, bv);
    l2norm_qk<<<NB / 256, 256>>>();
    row_sums<<<BB * (CQ + CO), 256>>>();
    kv_matrix<<<BB * CO, 256>>>();
    final_out<<<BB * (NN / 64), 256>>>(gamma, out);
}

// round 3
// speedup vs baseline: 2.9309x; 2.9309x over previous
#include <cuda_runtime.h>
#include <cuda_bf16.h>
#include <math.h>

#define BB   4
#define CIN  1024
#define CO   256
#define NN   16384          // H*W
#define NB   (BB*NN)        // 65536
#define CQ   32
#define FN   16384.0f
#define NSPLIT 32

// ---------------- scratch (device globals; no allocations allowed) ----------
__device__ float g_feat[BB*CO*NN];     // conv out -> BN'd feat
__device__ float g_Q[BB*CQ*NN];
__device__ float g_K[BB*CQ*NN];
__device__ float g_V[BB*CO*NN];
__device__ float g_scale[CO];
__device__ float g_shift[CO];
__device__ float g_Ksum[BB*CQ];
__device__ float g_Vsum[BB*CO];
__device__ float g_matrix[BB*CQ*CO];            // [b][q][c]
__device__ float g_mpart[NSPLIT*BB*CQ*CO];      // split-n partials

// ---------------- tf32 mma helpers ----------------------------------------
__device__ __forceinline__ unsigned f2tf(float f) {
    unsigned u;
    asm("cvt.rna.tf32.f32 %0, %1;" : "=r"(u) : "f"(f));
    return u;
}
__device__ __forceinline__ void mma_tf32(float* d, const unsigned* a, const unsigned* b) {
    asm("mma.sync.aligned.m16n8k8.row.col.f32.tf32.tf32.f32 "
        "{%0,%1,%2,%3}, {%4,%5,%6,%7}, {%8,%9}, {%0,%1,%2,%3};"
        : "+f"(d[0]), "+f"(d[1]), "+f"(d[2]), "+f"(d[3])
        : "r"(a[0]), "r"(a[1]), "r"(a[2]), "r"(a[3]), "r"(b[0]), "r"(b[1]));
}

// ---------------- 1: conv GEMM (tf32): feat[b,o,n] = sum_c w[o,c]*X[c,n] ---
// Block tile M=64(o) x N=128(n), K step 16. 8 warps as 2(M)x4(N), warp 32x32.
#define ASTR 68
#define BSTR 132
__global__ __launch_bounds__(256) void conv_gemm_tf32(
    const float* __restrict__ s5, const float* __restrict__ s4,
    const float* __restrict__ s3, const float* __restrict__ s2,
    const float* __restrict__ w)
{
    __shared__ unsigned As[16*ASTR];   // [k][o]
    __shared__ unsigned Bs[16*BSTR];   // [k][n]
    const int tid  = threadIdx.x;
    const int lane = tid & 31, warp = tid >> 5;
    const int wm = warp >> 2, wn = warp & 3;
    const int g = lane >> 2, c4 = lane & 3;
    const int m0 = blockIdx.x * 128;
    const int o0 = blockIdx.y * 64;
    const int b  = m0 >> 14;
    const int n0 = m0 & (NN - 1);

    float acc[2][4][4] = {};
    for (int k0 = 0; k0 < CIN; k0 += 16) {
        const float* src = (k0 < 256) ? s5 : (k0 < 512) ? s4 : (k0 < 768) ? s3 : s2;
        const int crem0 = k0 & 255;
        {   // A: 64 o x 16 k ; thread: o=tid>>2, 4 k's
            int o = tid >> 2, kq = (tid & 3) * 4;
            float4 v = *(const float4*)&w[(o0 + o) * CIN + k0 + kq];
            As[(kq+0)*ASTR + o] = f2tf(v.x);
            As[(kq+1)*ASTR + o] = f2tf(v.y);
            As[(kq+2)*ASTR + o] = f2tf(v.z);
            As[(kq+3)*ASTR + o] = f2tf(v.w);
        }
        #pragma unroll
        for (int l = 0; l < 2; l++) {   // B: 16 k x 128 n (512 float4)
            int idx = tid + l * 256;
            int kr = idx >> 5, nf = (idx & 31) * 4;
            float4 v = *(const float4*)&src[((b << 8) + crem0 + kr) * NN + n0 + nf];
            unsigned* d = &Bs[kr * BSTR + nf];
            d[0] = f2tf(v.x); d[1] = f2tf(v.y); d[2] = f2tf(v.z); d[3] = f2tf(v.w);
        }
        __syncthreads();
        #pragma unroll
        for (int ks = 0; ks < 16; ks += 8) {
            unsigned af[2][4], bf[4][2];
            #pragma unroll
            for (int mi = 0; mi < 2; mi++) {
                int m = wm * 32 + mi * 16 + g;
                af[mi][0] = As[(ks+c4  )*ASTR + m];
                af[mi][1] = As[(ks+c4  )*ASTR + m + 8];
                af[mi][2] = As[(ks+c4+4)*ASTR + m];
                af[mi][3] = As[(ks+c4+4)*ASTR + m + 8];
            }
            #pragma unroll
            for (int nj = 0; nj < 4; nj++) {
                int n = wn * 32 + nj * 8 + g;
                bf[nj][0] = Bs[(ks+c4  )*BSTR + n];
                bf[nj][1] = Bs[(ks+c4+4)*BSTR + n];
            }
            #pragma unroll
            for (int mi = 0; mi < 2; mi++)
                #pragma unroll
                for (int nj = 0; nj < 4; nj++)
                    mma_tf32(acc[mi][nj], af[mi], bf[nj]);
        }
        __syncthreads();
    }
    #pragma unroll
    for (int mi = 0; mi < 2; mi++) {
        int o1 = o0 + wm * 32 + mi * 16 + g;
        #pragma unroll
        for (int nj = 0; nj < 4; nj++) {
            int nn1 = n0 + wn * 32 + nj * 8 + c4 * 2;
            float* base = &g_feat[(b * CO + o1) * NN + nn1];
            *(float2*)base            = make_float2(acc[mi][nj][0], acc[mi][nj][1]);
            *(float2*)(base + 8 * NN) = make_float2(acc[mi][nj][2], acc[mi][nj][3]);
        }
    }
}

// ---------------- 2: per-channel BN stats -> scale/shift -------------------
__global__ __launch_bounds__(256) void bn_stats(
    const float* __restrict__ bn_gamma, const float* __restrict__ bn_beta)
{
    const int o = blockIdx.x;
    const int t = threadIdx.x;
    float s = 0.f, ss = 0.f;
    for (int b = 0; b < BB; b++) {
        const float* p = g_feat + (b * CO + o) * NN;
        for (int n = t; n < NN; n += 256) { float v = p[n]; s += v; ss += v * v; }
    }
    __shared__ float sh[256], sh2[256];
    sh[t] = s; sh2[t] = ss; __syncthreads();
    for (int st = 128; st > 0; st >>= 1) {
        if (t < st) { sh[t] += sh[t + st]; sh2[t] += sh2[t + st]; }
        __syncthreads();
    }
    if (t == 0) {
        const float inv = 1.0f / (float)(BB * NN);
        float mean = sh[0] * inv;
        float var  = sh2[0] * inv - mean * mean;
        float sc   = bn_gamma[o] * rsqrtf(var + 1e-5f);
        g_scale[o] = sc;
        g_shift[o] = bn_beta[o] - mean * sc;
    }
}

// ---------------- 3: BN + ReLU in place (float4) ---------------------------
__global__ __launch_bounds__(256) void bn_apply()
{
    int idx4 = blockIdx.x * 256 + threadIdx.x;
    int o = (idx4 >> 12) & 255;
    float sc = g_scale[o], sh = g_shift[o];
    float4 v = *(float4*)&g_feat[idx4 * 4];
    v.x = fmaxf(v.x * sc + sh, 0.f);
    v.y = fmaxf(v.y * sc + sh, 0.f);
    v.z = fmaxf(v.z * sc + sh, 0.f);
    v.w = fmaxf(v.w * sc + sh, 0.f);
    *(float4*)&g_feat[idx4 * 4] = v;
}

// ---------------- 4: fused QKV GEMM (tf32): 320 rows, K=256 ----------------
__device__ __forceinline__ float* qkv_dst(int r, int b,
    const float* bq, const float* bk, const float* bv, float& bias)
{
    if (r < 32) { bias = bq[r];      return &g_Q[(b * CQ + r) * NN]; }
    if (r < 64) { bias = bk[r - 32]; return &g_K[(b * CQ + r - 32) * NN]; }
    bias = bv[r - 64];               return &g_V[(b * CO + r - 64) * NN];
}

__global__ __launch_bounds__(256) void qkv_gemm_tf32(
    const float* __restrict__ wq, const float* __restrict__ bq,
    const float* __restrict__ wk, const float* __restrict__ bk,
    const float* __restrict__ wv, const float* __restrict__ bv)
{
    __shared__ unsigned As[16*ASTR];
    __shared__ unsigned Bs[16*BSTR];
    const int tid  = threadIdx.x;
    const int lane = tid & 31, warp = tid >> 5;
    const int wm = warp >> 2, wn = warp & 3;
    const int g = lane >> 2, c4 = lane & 3;
    const int m0 = blockIdx.x * 128;
    const int r0 = blockIdx.y * 64;     // 0..256
    const int b  = m0 >> 14;
    const int n0 = m0 & (NN - 1);

    float acc[2][4][4] = {};
    for (int k0 = 0; k0 < CO; k0 += 16) {
        {
            int o = tid >> 2, kq = (tid & 3) * 4;
            int r = r0 + o;
            const float* wrow = (r < 32) ? (wq + r * CO)
                              : (r < 64) ? (wk + (r - 32) * CO)
                                         : (wv + (r - 64) * CO);
            float4 v = *(const float4*)&wrow[k0 + kq];
            As[(kq+0)*ASTR + o] = f2tf(v.x);
            As[(kq+1)*ASTR + o] = f2tf(v.y);
            As[(kq+2)*ASTR + o] = f2tf(v.z);
            As[(kq+3)*ASTR + o] = f2tf(v.w);
        }
        #pragma unroll
        for (int l = 0; l < 2; l++) {
            int idx = tid + l * 256;
            int kr = idx >> 5, nf = (idx & 31) * 4;
            float4 v = *(const float4*)&g_feat[(b * CO + k0 + kr) * NN + n0 + nf];
            unsigned* d = &Bs[kr * BSTR + nf];
            d[0] = f2tf(v.x); d[1] = f2tf(v.y); d[2] = f2tf(v.z); d[3] = f2tf(v.w);
        }
        __syncthreads();
        #pragma unroll
        for (int ks = 0; ks < 16; ks += 8) {
            unsigned af[2][4], bf[4][2];
            #pragma unroll
            for (int mi = 0; mi < 2; mi++) {
                int m = wm * 32 + mi * 16 + g;
                af[mi][0] = As[(ks+c4  )*ASTR + m];
                af[mi][1] = As[(ks+c4  )*ASTR + m + 8];
                af[mi][2] = As[(ks+c4+4)*ASTR + m];
                af[mi][3] = As[(ks+c4+4)*ASTR + m + 8];
            }
            #pragma unroll
            for (int nj = 0; nj < 4; nj++) {
                int n = wn * 32 + nj * 8 + g;
                bf[nj][0] = Bs[(ks+c4  )*BSTR + n];
                bf[nj][1] = Bs[(ks+c4+4)*BSTR + n];
            }
            #pragma unroll
            for (int mi = 0; mi < 2; mi++)
                #pragma unroll
                for (int nj = 0; nj < 4; nj++)
                    mma_tf32(acc[mi][nj], af[mi], bf[nj]);
        }
        __syncthreads();
    }
    #pragma unroll
    for (int mi = 0; mi < 2; mi++) {
        int r1 = r0 + wm * 32 + mi * 16 + g;
        float bias1, bias2;
        float* d1 = qkv_dst(r1,     b, bq, bk, bv, bias1);
        float* d2 = qkv_dst(r1 + 8, b, bq, bk, bv, bias2);
        #pragma unroll
        for (int nj = 0; nj < 4; nj++) {
            int nn1 = n0 + wn * 32 + nj * 8 + c4 * 2;
            *(float2*)&d1[nn1] = make_float2(acc[mi][nj][0] + bias1, acc[mi][nj][1] + bias1);
            *(float2*)&d2[nn1] = make_float2(acc[mi][nj][2] + bias2, acc[mi][nj][3] + bias2);
        }
    }
}

// ---------------- 5: L2-normalize Q and K over channel dim -----------------
__global__ __launch_bounds__(256) void l2norm_qk()
{
    int col = blockIdx.x * 256 + threadIdx.x;
    int b = col >> 14, n = col & (NN - 1);
    {
        float* p = g_Q + b * CQ * NN + n;
        float v[CQ]; float s = 0.f;
        #pragma unroll
        for (int q = 0; q < CQ; q++) { v[q] = p[q * NN]; s += v[q] * v[q]; }
        float r = 1.f / fmaxf(sqrtf(s), 1e-6f);
        #pragma unroll
        for (int q = 0; q < CQ; q++) p[q * NN] = v[q] * r;
    }
    {
        float* p = g_K + b * CQ * NN + n;
        float v[CQ]; float s = 0.f;
        #pragma unroll
        for (int q = 0; q < CQ; q++) { v[q] = p[q * NN]; s += v[q] * v[q]; }
        float r = 1.f / fmaxf(sqrtf(s), 1e-6f);
        #pragma unroll
        for (int q = 0; q < CQ; q++) p[q * NN] = v[q] * r;
    }
}

// ---------------- 6: row sums: Ksum[b,q], Vsum[b,c] ------------------------
__global__ __launch_bounds__(256) void row_sums()
{
    const int id = blockIdx.x;
    const int b = id / (CQ + CO);
    const int r = id % (CQ + CO);
    const float* p; float* dst;
    if (r < CQ) { p = g_K + (b * CQ + r) * NN;        dst = &g_Ksum[b * CQ + r]; }
    else        { p = g_V + (b * CO + (r - CQ)) * NN; dst = &g_Vsum[b * CO + r - CQ]; }
    const int t = threadIdx.x;
    float s = 0.f;
    for (int n = t; n < NN; n += 256) s += p[n];
    __shared__ float sh[256];
    sh[t] = s; __syncthreads();
    for (int st = 128; st > 0; st >>= 1) {
        if (t < st) sh[t] += sh[t + st];
        __syncthreads();
    }
    if (t == 0) *dst = sh[0];
}

// ---------------- 7a: split-n KV GEMM (tf32): part[ns,b,q,c] ---------------
// Per block: b, n-range 512. M=32(q) x N=256(c), K=n. 8 warps, warp = 32 c.
#define KSTR 36
__global__ __launch_bounds__(256) void kv_partial()
{
    const int ns = blockIdx.x;          // 0..31
    const int b  = blockIdx.y;          // 0..3
    const int n_start = ns * (NN / NSPLIT);   // 512-range
    __shared__ unsigned Ks[32*KSTR];    // [q][n] chunk 32
    __shared__ unsigned Vs[256*KSTR];   // [c][n]
    const int t = threadIdx.x;
    const int lane = t & 31, warp = t >> 5;
    const int g = lane >> 2, c4 = lane & 3;

    float acc[2][4][4] = {};
    for (int ch = 0; ch < NN / NSPLIT; ch += 32) {
        const int n0c = n_start + ch;
        {   // K: 32 rows x 8 f4
            int row = t >> 3, f = t & 7;
            float4 v = *(const float4*)&g_K[(b * CQ + row) * NN + n0c + f * 4];
            unsigned* d = &Ks[row * KSTR + f * 4];
            d[0] = f2tf(v.x); d[1] = f2tf(v.y); d[2] = f2tf(v.z); d[3] = f2tf(v.w);
        }
        #pragma unroll
        for (int l = 0; l < 8; l++) {   // V: 256 rows x 8 f4
            int idx = t + l * 256;
            int row = idx >> 3, f = idx & 7;
            float4 v = *(const float4*)&g_V[(b * CO + row) * NN + n0c + f * 4];
            unsigned* d = &Vs[row * KSTR + f * 4];
            d[0] = f2tf(v.x); d[1] = f2tf(v.y); d[2] = f2tf(v.z); d[3] = f2tf(v.w);
        }
        __syncthreads();
        #pragma unroll
        for (int ks = 0; ks < 32; ks += 8) {
            unsigned af[2][4], bf[4][2];
            #pragma unroll
            for (int mi = 0; mi < 2; mi++) {
                int r = mi * 16 + g;
                af[mi][0] = Ks[ r      * KSTR + ks + c4];
                af[mi][1] = Ks[(r + 8) * KSTR + ks + c4];
                af[mi][2] = Ks[ r      * KSTR + ks + c4 + 4];
                af[mi][3] = Ks[(r + 8) * KSTR + ks + c4 + 4];
            }
            #pragma unroll
            for (int nj = 0; nj < 4; nj++) {
                int c = warp * 32 + nj * 8 + g;
                bf[nj][0] = Vs[c * KSTR + ks + c4];
                bf[nj][1] = Vs[c * KSTR + ks + c4 + 4];
            }
            #pragma unroll
            for (int mi = 0; mi < 2; mi++)
                #pragma unroll
                for (int nj = 0; nj < 4; nj++)
                    mma_tf32(acc[mi][nj], af[mi], bf[nj]);
        }
        __syncthreads();
    }
    const int pbase = (ns * BB + b) * CQ * CO;
    #pragma unroll
    for (int mi = 0; mi < 2; mi++) {
        int q = mi * 16 + g;
        #pragma unroll
        for (int nj = 0; nj < 4; nj++) {
            int c = warp * 32 + nj * 8 + c4 * 2;
            *(float2*)&g_mpart[pbase + q * CO + c]       = make_float2(acc[mi][nj][0], acc[mi][nj][1]);
            *(float2*)&g_mpart[pbase + (q + 8) * CO + c] = make_float2(acc[mi][nj][2], acc[mi][nj][3]);
        }
    }
}

// ---------------- 7b: reduce partials -> g_matrix --------------------------
__global__ __launch_bounds__(256) void kv_reduce()
{
    int idx = blockIdx.x * 256 + threadIdx.x;   // 0..BB*CQ*CO-1
    float s = 0.f;
    #pragma unroll
    for (int ns = 0; ns < NSPLIT; ns++) s += g_mpart[ns * (BB * CQ * CO) + idx];
    g_matrix[idx] = s;
}

// ---------------- 8: final: out = feat + nan2num(gamma*(Vsum + Qn.M)*tail) -
__global__ __launch_bounds__(256) void final_out2(
    const float* __restrict__ gamma_p, float* __restrict__ out)
{
    const int b  = blockIdx.y;
    const int n0 = blockIdx.x * 64;
    __shared__ float qsh[CQ * 64];       // [q][n]
    __shared__ float msh[CO * 33];       // [c][q] stride 33
    __shared__ float vsum_sh[CO], ksum_sh[CQ];
    __shared__ float tail[64];
    const int t = threadIdx.x;

    #pragma unroll
    for (int l = 0; l < 2; l++) {        // Qn tile: 512 float4
        int idx = t + l * 256;
        int q = idx >> 4, nf = (idx & 15) * 4;
        *(float4*)&qsh[q * 64 + nf] = *(const float4*)&g_Q[(b * CQ + q) * NN + n0 + nf];
    }
    #pragma unroll
    for (int l = 0; l < 32; l++) {       // matrix transposed into [c][q]
        int idx = t + l * 256;           // idx = q*CO + c
        int q = idx >> 8, c = idx & 255;
        msh[c * 33 + q] = g_matrix[b * CQ * CO + idx];
    }
    if (t < CO) vsum_sh[t] = g_Vsum[b * CO + t];
    if (t < CQ) ksum_sh[t] = g_Ksum[b * CQ + t];
    __syncthreads();
    if (t < 64) {
        float e = 0.f;
        #pragma unroll
        for (int q = 0; q < CQ; q++) e += qsh[q * 64 + t] * ksum_sh[q];
        tail[t] = 1.f / fmaxf(FN + e, 1e-6f);
    }
    __syncthreads();

    const int tc = t >> 3, tn = t & 7;   // 8c x 8n per thread
    float acc[8][8] = {};
    #pragma unroll 4
    for (int q = 0; q < CQ; q++) {
        float4 qa = *(const float4*)&qsh[q * 64 + tn * 8];
        float4 qb = *(const float4*)&qsh[q * 64 + tn * 8 + 4];
        float qv[8] = {qa.x, qa.y, qa.z, qa.w, qb.x, qb.y, qb.z, qb.w};
        #pragma unroll
        for (int cc = 0; cc < 8; cc++) {
            float mv = msh[(tc * 8 + cc) * 33 + q];
            #pragma unroll
            for (int nn = 0; nn < 8; nn++) acc[cc][nn] += mv * qv[nn];
        }
    }
    const float gam = gamma_p[0];
    #pragma unroll
    for (int cc = 0; cc < 8; cc++) {
        int c = tc * 8 + cc;
        float vs = vsum_sh[c];
        int base = (b * CO + c) * NN + n0 + tn * 8;
        float4 f1 = *(const float4*)&g_feat[base];
        float4 f2 = *(const float4*)&g_feat[base + 4];
        float r[8];
        #pragma unroll
        for (int nn = 0; nn < 8; nn++) {
            float v = gam * (vs + acc[cc][nn]) * tail[tn * 8 + nn];
            if (isnan(v)) v = 0.f;
            else if (isinf(v)) v = (v > 0.f) ? 1.f : -1.f;
            r[nn] = v;
        }
        *(float4*)&out[base]     = make_float4(r[0] + f1.x, r[1] + f1.y, r[2] + f1.z, r[3] + f1.w);
        *(float4*)&out[base + 4] = make_float4(r[4] + f2.x, r[5] + f2.y, r[6] + f2.z, r[7] + f2.w);
    }
}

// ---------------------------------------------------------------------------
extern "C" void kernel_launch(void* const* d_in, const int* in_sizes, int n_in,
                              void* d_out, int out_size)
{
    const float* s5       = (const float*)d_in[0];
    const float* s4       = (const float*)d_in[1];
    const float* s3       = (const float*)d_in[2];
    const float* s2       = (const float*)d_in[3];
    const float* w_conv   = (const float*)d_in[4];
    const float* bn_gamma = (const float*)d_in[5];
    const float* bn_beta  = (const float*)d_in[6];
    const float* wq       = (const float*)d_in[7];
    const float* bq       = (const float*)d_in[8];
    const float* wk       = (const float*)d_in[9];
    const float* bk       = (const float*)d_in[10];
    const float* wv       = (const float*)d_in[11];
    const float* bv       = (const float*)d_in[12];
    const float* gamma    = (const float*)d_in[13];
    float* out = (float*)d_out;

    conv_gemm_tf32<<<dim3(NB / 128, CO / 64), 256>>>(s5, s4, s3, s2, w_conv);
    bn_stats<<<CO, 256>>>(bn_gamma, bn_beta);
    bn_apply<<<(BB * CO * NN / 4) / 256, 256>>>();
    qkv_gemm_tf32<<<dim3(NB / 128, 5), 256>>>(wq, bq, wk, bk, wv, bv);
    l2norm_qk<<<NB / 256, 256>>>();
    row_sums<<<BB * (CQ + CO), 256>>>();
    kv_partial<<<dim3(NSPLIT, BB), 256>>>();
    kv_reduce<<<(BB * CQ * CO) / 256, 256>>>();
    final_out2<<<dim3(NN / 64, BB), 256>>>(gamma, out);
}

// round 5
// speedup vs baseline: 3.0242x; 1.0318x over previous
#include <cuda_runtime.h>
#include <cuda_bf16.h>
#include <math.h>

#define BB   4
#define CIN  1024
#define CO   256
#define NN   16384          // H*W
#define NB   (BB*NN)        // 65536
#define CQ   32
#define FN   16384.0f
#define NSPLIT 32

// ---------------- scratch (device globals; no allocations allowed) ----------
__device__ float g_feat[BB*CO*NN];     // RAW conv out (BN applied on the fly)
__device__ float g_Q[BB*CQ*NN];
__device__ float g_K[BB*CQ*NN];
__device__ float g_V[BB*CO*NN];
__device__ float g_scale[CO];
__device__ float g_shift[CO];
__device__ float g_Ksum[BB*CQ];
__device__ float g_Vsum[BB*CO];
__device__ float g_matrix[BB*CQ*CO];            // [b][q][c]
__device__ float g_mpart[NSPLIT*BB*CQ*CO];      // split-n partials

// ---------------- tf32 mma helpers ----------------------------------------
__device__ __forceinline__ unsigned f2tf(float f) {
    unsigned u;
    asm("cvt.rna.tf32.f32 %0, %1;" : "=r"(u) : "f"(f));
    return u;
}
__device__ __forceinline__ void mma_tf32(float* d, const unsigned* a, const unsigned* b) {
    asm("mma.sync.aligned.m16n8k8.row.col.f32.tf32.tf32.f32 "
        "{%0,%1,%2,%3}, {%4,%5,%6,%7}, {%8,%9}, {%0,%1,%2,%3};"
        : "+f"(d[0]), "+f"(d[1]), "+f"(d[2]), "+f"(d[3])
        : "r"(a[0]), "r"(a[1]), "r"(a[2]), "r"(a[3]), "r"(b[0]), "r"(b[1]));
}

// ===========================================================================
// 1: conv GEMM (tf32): feat[b,o,n] = sum_c w[o,c]*X[c,n]
// Block 128(o) x 128(n), k-step 16, double-buffered. 8 warps 2x4, warp 64x32.
// Strides 136 == 8 (mod 32): conflict-free c4-row fragment loads.
// ===========================================================================
#define CSTR 136
__global__ __launch_bounds__(256, 2) void conv_gemm_tf32(
    const float* __restrict__ s5, const float* __restrict__ s4,
    const float* __restrict__ s3, const float* __restrict__ s2,
    const float* __restrict__ w)
{
    __shared__ unsigned As[2][16*CSTR];   // [k][o]
    __shared__ unsigned Bs[2][16*CSTR];   // [k][n]
    const int tid  = threadIdx.x;
    const int lane = tid & 31, warp = tid >> 5;
    const int wm = warp >> 2, wn = warp & 3;       // 2 x 4
    const int g = lane >> 2, c4 = lane & 3;
    const int m0 = blockIdx.x * 128;
    const int o0 = blockIdx.y * 128;
    const int b  = m0 >> 14;
    const int n0 = m0 & (NN - 1);

    // prefetch mappings
    const int ao = tid & 127, ak = (tid >> 7) * 8;  // A: col ao, k ak..ak+7
    const int bk = tid >> 4,  bn = (tid & 15) * 8;  // B: row bk, n bn..bn+7

    float4 pa0, pa1, pb0, pb1;
    {   // tile 0 (k0=0 -> s5)
        const float* ar = &w[(o0 + ao) * CIN + ak];
        pa0 = *(const float4*)ar; pa1 = *(const float4*)(ar + 4);
        const float* br = &s5[((b << 8) + bk) * NN + n0 + bn];
        pb0 = *(const float4*)br; pb1 = *(const float4*)(br + 4);
    }
    {   // stage 0 STS
        As[0][(ak+0)*CSTR+ao]=f2tf(pa0.x); As[0][(ak+1)*CSTR+ao]=f2tf(pa0.y);
        As[0][(ak+2)*CSTR+ao]=f2tf(pa0.z); As[0][(ak+3)*CSTR+ao]=f2tf(pa0.w);
        As[0][(ak+4)*CSTR+ao]=f2tf(pa1.x); As[0][(ak+5)*CSTR+ao]=f2tf(pa1.y);
        As[0][(ak+6)*CSTR+ao]=f2tf(pa1.z); As[0][(ak+7)*CSTR+ao]=f2tf(pa1.w);
        unsigned* d = &Bs[0][bk*CSTR+bn];
        d[0]=f2tf(pb0.x); d[1]=f2tf(pb0.y); d[2]=f2tf(pb0.z); d[3]=f2tf(pb0.w);
        d[4]=f2tf(pb1.x); d[5]=f2tf(pb1.y); d[6]=f2tf(pb1.z); d[7]=f2tf(pb1.w);
    }
    __syncthreads();

    float acc[4][4][4] = {};
    for (int t = 0; t < 64; t++) {
        const int buf = t & 1;
        if (t < 63) {   // prefetch tile t+1
            const int k0 = (t + 1) * 16;
            const float* src = (k0 < 256) ? s5 : (k0 < 512) ? s4 : (k0 < 768) ? s3 : s2;
            const int crem = k0 & 255;
            const float* ar = &w[(o0 + ao) * CIN + k0 + ak];
            pa0 = *(const float4*)ar; pa1 = *(const float4*)(ar + 4);
            const float* br = &src[((b << 8) + crem + bk) * NN + n0 + bn];
            pb0 = *(const float4*)br; pb1 = *(const float4*)(br + 4);
        }
        #pragma unroll
        for (int ks = 0; ks < 16; ks += 8) {
            unsigned af[4][4], bf[4][2];
            #pragma unroll
            for (int mi = 0; mi < 4; mi++) {
                int m = wm * 64 + mi * 16 + g;
                af[mi][0] = As[buf][(ks+c4  )*CSTR + m];
                af[mi][1] = As[buf][(ks+c4  )*CSTR + m + 8];
                af[mi][2] = As[buf][(ks+c4+4)*CSTR + m];
                af[mi][3] = As[buf][(ks+c4+4)*CSTR + m + 8];
            }
            #pragma unroll
            for (int nj = 0; nj < 4; nj++) {
                int n = wn * 32 + nj * 8 + g;
                bf[nj][0] = Bs[buf][(ks+c4  )*CSTR + n];
                bf[nj][1] = Bs[buf][(ks+c4+4)*CSTR + n];
            }
            #pragma unroll
            for (int mi = 0; mi < 4; mi++)
                #pragma unroll
                for (int nj = 0; nj < 4; nj++)
                    mma_tf32(acc[mi][nj], af[mi], bf[nj]);
        }
        if (t < 63) {
            const int nb = buf ^ 1;
            As[nb][(ak+0)*CSTR+ao]=f2tf(pa0.x); As[nb][(ak+1)*CSTR+ao]=f2tf(pa0.y);
            As[nb][(ak+2)*CSTR+ao]=f2tf(pa0.z); As[nb][(ak+3)*CSTR+ao]=f2tf(pa0.w);
            As[nb][(ak+4)*CSTR+ao]=f2tf(pa1.x); As[nb][(ak+5)*CSTR+ao]=f2tf(pa1.y);
            As[nb][(ak+6)*CSTR+ao]=f2tf(pa1.z); As[nb][(ak+7)*CSTR+ao]=f2tf(pa1.w);
            unsigned* d = &Bs[nb][bk*CSTR+bn];
            d[0]=f2tf(pb0.x); d[1]=f2tf(pb0.y); d[2]=f2tf(pb0.z); d[3]=f2tf(pb0.w);
            d[4]=f2tf(pb1.x); d[5]=f2tf(pb1.y); d[6]=f2tf(pb1.z); d[7]=f2tf(pb1.w);
            __syncthreads();
        }
    }
    #pragma unroll
    for (int mi = 0; mi < 4; mi++) {
        int o1 = o0 + wm * 64 + mi * 16 + g;
        #pragma unroll
        for (int nj = 0; nj < 4; nj++) {
            int nn1 = n0 + wn * 32 + nj * 8 + c4 * 2;
            float* base = &g_feat[(b * CO + o1) * NN + nn1];
            *(float2*)base            = make_float2(acc[mi][nj][0], acc[mi][nj][1]);
            *(float2*)(base + 8 * NN) = make_float2(acc[mi][nj][2], acc[mi][nj][3]);
        }
    }
}

// ---------------- 2: per-channel BN stats -> scale/shift -------------------
__global__ __launch_bounds__(256) void bn_stats(
    const float* __restrict__ bn_gamma, const float* __restrict__ bn_beta)
{
    const int o = blockIdx.x;
    const int t = threadIdx.x;
    float s = 0.f, ss = 0.f;
    for (int b = 0; b < BB; b++) {
        const float* p = g_feat + (b * CO + o) * NN;
        for (int n = t; n < NN; n += 256) { float v = p[n]; s += v; ss += v * v; }
    }
    __shared__ float sh[256], sh2[256];
    sh[t] = s; sh2[t] = ss; __syncthreads();
    for (int st = 128; st > 0; st >>= 1) {
        if (t < st) { sh[t] += sh[t + st]; sh2[t] += sh2[t + st]; }
        __syncthreads();
    }
    if (t == 0) {
        const float inv = 1.0f / (float)(BB * NN);
        float mean = sh[0] * inv;
        float var  = sh2[0] * inv - mean * mean;
        float sc   = bn_gamma[o] * rsqrtf(var + 1e-5f);
        g_scale[o] = sc;
        g_shift[o] = bn_beta[o] - mean * sc;
    }
}

// ===========================================================================
// 3: fused QKV GEMM (tf32), BN+ReLU applied to feat inline while staging B.
// Block 64(r) x 256(n), k-step 16, double-buffered. 8 warps 2x4, warp 32x64.
// ===========================================================================
#define QASTR 72    // 72 % 32 == 8
#define QBSTR 264   // 264 % 32 == 8
__device__ __forceinline__ float* qkv_dst(int r, int b,
    const float* bq, const float* bk, const float* bv, float& bias)
{
    if (r < 32) { bias = bq[r];      return &g_Q[(b * CQ + r) * NN]; }
    if (r < 64) { bias = bk[r - 32]; return &g_K[(b * CQ + r - 32) * NN]; }
    bias = bv[r - 64];               return &g_V[(b * CO + r - 64) * NN];
}

__global__ __launch_bounds__(256, 2) void qkv_gemm_tf32(
    const float* __restrict__ wq, const float* __restrict__ bq,
    const float* __restrict__ wk, const float* __restrict__ bk,
    const float* __restrict__ wv, const float* __restrict__ bv)
{
    __shared__ unsigned As[2][16*QASTR];
    __shared__ unsigned Bs[2][16*QBSTR];
    const int tid  = threadIdx.x;
    const int lane = tid & 31, warp = tid >> 5;
    const int wm = warp >> 2, wn = warp & 3;     // 2 x 4 warps, warp 32m x 64n
    const int g = lane >> 2, c4 = lane & 3;
    const int m0 = blockIdx.x * 256;
    const int r0 = blockIdx.y * 64;              // 0..256 step 64 (5 blocks)
    const int b  = m0 >> 14;
    const int n0 = m0 & (NN - 1);

    const int ao = tid & 63,  ak = (tid >> 6) * 4;    // A: col ao, k ak..ak+3
    const int bkr = tid >> 4, bnf = (tid & 15) * 16;  // B: row bkr, n bnf..bnf+15

    const int ar = r0 + ao;
    const float* wrow = (ar < 32) ? (wq + ar * CO)
                      : (ar < 64) ? (wk + (ar - 32) * CO)
                                  : (wv + (ar - 64) * CO);

    float4 pa, pb[4]; float psc, psh;
    {
        pa = *(const float4*)&wrow[ak];
        psc = g_scale[bkr]; psh = g_shift[bkr];
        const float* br = &g_feat[(b * CO + bkr) * NN + n0 + bnf];
        #pragma unroll
        for (int j = 0; j < 4; j++) pb[j] = *(const float4*)(br + j * 4);
    }
    {
        As[0][(ak+0)*QASTR+ao]=f2tf(pa.x); As[0][(ak+1)*QASTR+ao]=f2tf(pa.y);
        As[0][(ak+2)*QASTR+ao]=f2tf(pa.z); As[0][(ak+3)*QASTR+ao]=f2tf(pa.w);
        unsigned* d = &Bs[0][bkr*QBSTR+bnf];
        #pragma unroll
        for (int j = 0; j < 4; j++) {
            d[j*4+0]=f2tf(fmaxf(fmaf(pb[j].x,psc,psh),0.f));
            d[j*4+1]=f2tf(fmaxf(fmaf(pb[j].y,psc,psh),0.f));
            d[j*4+2]=f2tf(fmaxf(fmaf(pb[j].z,psc,psh),0.f));
            d[j*4+3]=f2tf(fmaxf(fmaf(pb[j].w,psc,psh),0.f));
        }
    }
    __syncthreads();

    float acc[2][8][4] = {};
    for (int t = 0; t < 16; t++) {
        const int buf = t & 1;
        if (t < 15) {
            const int k0 = (t + 1) * 16;
            pa = *(const float4*)&wrow[k0 + ak];
            psc = g_scale[k0 + bkr]; psh = g_shift[k0 + bkr];
            const float* br = &g_feat[(b * CO + k0 + bkr) * NN + n0 + bnf];
            #pragma unroll
            for (int j = 0; j < 4; j++) pb[j] = *(const float4*)(br + j * 4);
        }
        #pragma unroll
        for (int ks = 0; ks < 16; ks += 8) {
            unsigned af[2][4], bf[8][2];
            #pragma unroll
            for (int mi = 0; mi < 2; mi++) {
                int m = wm * 32 + mi * 16 + g;
                af[mi][0] = As[buf][(ks+c4  )*QASTR + m];
                af[mi][1] = As[buf][(ks+c4  )*QASTR + m + 8];
                af[mi][2] = As[buf][(ks+c4+4)*QASTR + m];
                af[mi][3] = As[buf][(ks+c4+4)*QASTR + m + 8];
            }
            #pragma unroll
            for (int nj = 0; nj < 8; nj++) {
                int n = wn * 64 + nj * 8 + g;
                bf[nj][0] = Bs[buf][(ks+c4  )*QBSTR + n];
                bf[nj][1] = Bs[buf][(ks+c4+4)*QBSTR + n];
            }
            #pragma unroll
            for (int mi = 0; mi < 2; mi++)
                #pragma unroll
                for (int nj = 0; nj < 8; nj++)
                    mma_tf32(acc[mi][nj], af[mi], bf[nj]);
        }
        if (t < 15) {
            const int nb = buf ^ 1;
            As[nb][(ak+0)*QASTR+ao]=f2tf(pa.x); As[nb][(ak+1)*QASTR+ao]=f2tf(pa.y);
            As[nb][(ak+2)*QASTR+ao]=f2tf(pa.z); As[nb][(ak+3)*QASTR+ao]=f2tf(pa.w);
            unsigned* d = &Bs[nb][bkr*QBSTR+bnf];
            #pragma unroll
            for (int j = 0; j < 4; j++) {
                d[j*4+0]=f2tf(fmaxf(fmaf(pb[j].x,psc,psh),0.f));
                d[j*4+1]=f2tf(fmaxf(fmaf(pb[j].y,psc,psh),0.f));
                d[j*4+2]=f2tf(fmaxf(fmaf(pb[j].z,psc,psh),0.f));
                d[j*4+3]=f2tf(fmaxf(fmaf(pb[j].w,psc,psh),0.f));
            }
            __syncthreads();
        }
    }
    #pragma unroll
    for (int mi = 0; mi < 2; mi++) {
        int r1 = r0 + wm * 32 + mi * 16 + g;
        float bias1, bias2;
        float* d1 = qkv_dst(r1,     b, bq, bk, bv, bias1);
        float* d2 = qkv_dst(r1 + 8, b, bq, bk, bv, bias2);
        #pragma unroll
        for (int nj = 0; nj < 8; nj++) {
            int nn1 = n0 + wn * 64 + nj * 8 + c4 * 2;
            *(float2*)&d1[nn1] = make_float2(acc[mi][nj][0] + bias1, acc[mi][nj][1] + bias1);
            *(float2*)&d2[nn1] = make_float2(acc[mi][nj][2] + bias2, acc[mi][nj][3] + bias2);
        }
    }
}

// ---------------- 4: L2-normalize Q and K over channel dim -----------------
__global__ __launch_bounds__(256) void l2norm_qk()
{
    int col = blockIdx.x * 256 + threadIdx.x;
    int b = col >> 14, n = col & (NN - 1);
    {
        float* p = g_Q + b * CQ * NN + n;
        float v[CQ]; float s = 0.f;
        #pragma unroll
        for (int q = 0; q < CQ; q++) { v[q] = p[q * NN]; s += v[q] * v[q]; }
        float r = 1.f / fmaxf(sqrtf(s), 1e-6f);
        #pragma unroll
        for (int q = 0; q < CQ; q++) p[q * NN] = v[q] * r;
    }
    {
        float* p = g_K + b * CQ * NN + n;
        float v[CQ]; float s = 0.f;
        #pragma unroll
        for (int q = 0; q < CQ; q++) { v[q] = p[q * NN]; s += v[q] * v[q]; }
        float r = 1.f / fmaxf(sqrtf(s), 1e-6f);
        #pragma unroll
        for (int q = 0; q < CQ; q++) p[q * NN] = v[q] * r;
    }
}

// ---------------- 5: row sums: Ksum[b,q], Vsum[b,c] ------------------------
__global__ __launch_bounds__(256) void row_sums()
{
    const int id = blockIdx.x;
    const int b = id / (CQ + CO);
    const int r = id % (CQ + CO);
    const float* p; float* dst;
    if (r < CQ) { p = g_K + (b * CQ + r) * NN;        dst = &g_Ksum[b * CQ + r]; }
    else        { p = g_V + (b * CO + (r - CQ)) * NN; dst = &g_Vsum[b * CO + r - CQ]; }
    const int t = threadIdx.x;
    float s = 0.f;
    for (int n = t; n < NN; n += 256) s += p[n];
    __shared__ float sh[256];
    sh[t] = s; __syncthreads();
    for (int st = 128; st > 0; st >>= 1) {
        if (t < st) sh[t] += sh[t + st];
        __syncthreads();
    }
    if (t == 0) *dst = sh[0];
}

// ---------------- 6a: split-n KV GEMM (tf32): part[ns,b,q,c] ---------------
#define KSTR 36
__global__ __launch_bounds__(256) void kv_partial()
{
    const int ns = blockIdx.x;
    const int b  = blockIdx.y;
    const int n_start = ns * (NN / NSPLIT);
    __shared__ unsigned Ks[32*KSTR];
    __shared__ unsigned Vs[256*KSTR];
    const int t = threadIdx.x;
    const int lane = t & 31, warp = t >> 5;
    const int g = lane >> 2, c4 = lane & 3;

    float acc[2][4][4] = {};
    for (int ch = 0; ch < NN / NSPLIT; ch += 32) {
        const int n0c = n_start + ch;
        {
            int row = t >> 3, f = t & 7;
            float4 v = *(const float4*)&g_K[(b * CQ + row) * NN + n0c + f * 4];
            unsigned* d = &Ks[row * KSTR + f * 4];
            d[0] = f2tf(v.x); d[1] = f2tf(v.y); d[2] = f2tf(v.z); d[3] = f2tf(v.w);
        }
        #pragma unroll
        for (int l = 0; l < 8; l++) {
            int idx = t + l * 256;
            int row = idx >> 3, f = idx & 7;
            float4 v = *(const float4*)&g_V[(b * CO + row) * NN + n0c + f * 4];
            unsigned* d = &Vs[row * KSTR + f * 4];
            d[0] = f2tf(v.x); d[1] = f2tf(v.y); d[2] = f2tf(v.z); d[3] = f2tf(v.w);
        }
        __syncthreads();
        #pragma unroll
        for (int ks = 0; ks < 32; ks += 8) {
            unsigned af[2][4], bf[4][2];
            #pragma unroll
            for (int mi = 0; mi < 2; mi++) {
                int r = mi * 16 + g;
                af[mi][0] = Ks[ r      * KSTR + ks + c4];
                af[mi][1] = Ks[(r + 8) * KSTR + ks + c4];
                af[mi][2] = Ks[ r      * KSTR + ks + c4 + 4];
                af[mi][3] = Ks[(r + 8) * KSTR + ks + c4 + 4];
            }
            #pragma unroll
            for (int nj = 0; nj < 4; nj++) {
                int c = warp * 32 + nj * 8 + g;
                bf[nj][0] = Vs[c * KSTR + ks + c4];
                bf[nj][1] = Vs[c * KSTR + ks + c4 + 4];
            }
            #pragma unroll
            for (int mi = 0; mi < 2; mi++)
                #pragma unroll
                for (int nj = 0; nj < 4; nj++)
                    mma_tf32(acc[mi][nj], af[mi], bf[nj]);
        }
        __syncthreads();
    }
    const int pbase = (ns * BB + b) * CQ * CO;
    #pragma unroll
    for (int mi = 0; mi < 2; mi++) {
        int q = mi * 16 + g;
        #pragma unroll
        for (int nj = 0; nj < 4; nj++) {
            int c = warp * 32 + nj * 8 + c4 * 2;
            *(float2*)&g_mpart[pbase + q * CO + c]       = make_float2(acc[mi][nj][0], acc[mi][nj][1]);
            *(float2*)&g_mpart[pbase + (q + 8) * CO + c] = make_float2(acc[mi][nj][2], acc[mi][nj][3]);
        }
    }
}

// ---------------- 6b: reduce partials -> g_matrix --------------------------
__global__ __launch_bounds__(256) void kv_reduce()
{
    int idx = blockIdx.x * 256 + threadIdx.x;
    float s = 0.f;
    #pragma unroll
    for (int ns = 0; ns < NSPLIT; ns++) s += g_mpart[ns * (BB * CQ * CO) + idx];
    g_matrix[idx] = s;
}

// ---------------- 7: final: out = featBN + nan2num(gamma*(Vsum+Qn.M)*tail) -
__global__ __launch_bounds__(256) void final_out2(
    const float* __restrict__ gamma_p, float* __restrict__ out)
{
    const int b  = blockIdx.y;
    const int n0 = blockIdx.x * 64;
    __shared__ float qsh[CQ * 64];       // [q][n]
    __shared__ float msh[CO * 33];       // [c][q] stride 33
    __shared__ float vsum_sh[CO], ksum_sh[CQ];
    __shared__ float tail[64];
    const int t = threadIdx.x;

    #pragma unroll
    for (int l = 0; l < 2; l++) {
        int idx = t + l * 256;
        int q = idx >> 4, nf = (idx & 15) * 4;
        *(float4*)&qsh[q * 64 + nf] = *(const float4*)&g_Q[(b * CQ + q) * NN + n0 + nf];
    }
    #pragma unroll
    for (int l = 0; l < 32; l++) {
        int idx = t + l * 256;           // idx = q*CO + c
        int q = idx >> 8, c = idx & 255;
        msh[c * 33 + q] = g_matrix[b * CQ * CO + idx];
    }
    if (t < CO) vsum_sh[t] = g_Vsum[b * CO + t];
    if (t < CQ) ksum_sh[t] = g_Ksum[b * CQ + t];
    __syncthreads();
    if (t < 64) {
        float e = 0.f;
        #pragma unroll
        for (int q = 0; q < CQ; q++) e += qsh[q * 64 + t] * ksum_sh[q];
        tail[t] = 1.f / fmaxf(FN + e, 1e-6f);
    }
    __syncthreads();

    const int tc = t >> 3, tn = t & 7;   // 8c x 8n per thread
    float acc[8][8] = {};
    #pragma unroll 4
    for (int q = 0; q < CQ; q++) {
        float4 qa = *(const float4*)&qsh[q * 64 + tn * 8];
        float4 qb = *(const float4*)&qsh[q * 64 + tn * 8 + 4];
        float qv[8] = {qa.x, qa.y, qa.z, qa.w, qb.x, qb.y, qb.z, qb.w};
        #pragma unroll
        for (int cc = 0; cc < 8; cc++) {
            float mv = msh[(tc * 8 + cc) * 33 + q];
            #pragma unroll
            for (int nn = 0; nn < 8; nn++) acc[cc][nn] += mv * qv[nn];
        }
    }
    const float gam = gamma_p[0];
    #pragma unroll
    for (int cc = 0; cc < 8; cc++) {
        int c = tc * 8 + cc;
        float vs = vsum_sh[c];
        float sc = g_scale[c], sh = g_shift[c];
        int base = (b * CO + c) * NN + n0 + tn * 8;
        float4 f1 = *(const float4*)&g_feat[base];
        float4 f2 = *(const float4*)&g_feat[base + 4];
        float fr[8] = {
            fmaxf(fmaf(f1.x,sc,sh),0.f), fmaxf(fmaf(f1.y,sc,sh),0.f),
            fmaxf(fmaf(f1.z,sc,sh),0.f), fmaxf(fmaf(f1.w,sc,sh),0.f),
            fmaxf(fmaf(f2.x,sc,sh),0.f), fmaxf(fmaf(f2.y,sc,sh),0.f),
            fmaxf(fmaf(f2.z,sc,sh),0.f), fmaxf(fmaf(f2.w,sc,sh),0.f)};
        float r[8];
        #pragma unroll
        for (int nn = 0; nn < 8; nn++) {
            float v = gam * (vs + acc[cc][nn]) * tail[tn * 8 + nn];
            if (isnan(v)) v = 0.f;
            else if (isinf(v)) v = (v > 0.f) ? 1.f : -1.f;
            r[nn] = v + fr[nn];
        }
        *(float4*)&out[base]     = make_float4(r[0], r[1], r[2], r[3]);
        *(float4*)&out[base + 4] = make_float4(r[4], r[5], r[6], r[7]);
    }
}

// ---------------------------------------------------------------------------
extern "C" void kernel_launch(void* const* d_in, const int* in_sizes, int n_in,
                              void* d_out, int out_size)
{
    const float* s5       = (const float*)d_in[0];
    const float* s4       = (const float*)d_in[1];
    const float* s3       = (const float*)d_in[2];
    const float* s2       = (const float*)d_in[3];
    const float* w_conv   = (const float*)d_in[4];
    const float* bn_gamma = (const float*)d_in[5];
    const float* bn_beta  = (const float*)d_in[6];
    const float* wq       = (const float*)d_in[7];
    const float* bq       = (const float*)d_in[8];
    const float* wk       = (const float*)d_in[9];
    const float* bk       = (const float*)d_in[10];
    const float* wv       = (const float*)d_in[11];
    const float* bv       = (const float*)d_in[12];
    const float* gamma    = (const float*)d_in[13];
    float* out = (float*)d_out;

    conv_gemm_tf32<<<dim3(NB / 128, CO / 128), 256>>>(s5, s4, s3, s2, w_conv);
    bn_stats<<<CO, 256>>>(bn_gamma, bn_beta);
    qkv_gemm_tf32<<<dim3(NB / 256, 5), 256>>>(wq, bq, wk, bk, wv, bv);
    l2norm_qk<<<NB / 256, 256>>>();
    row_sums<<<BB * (CQ + CO), 256>>>();
    kv_partial<<<dim3(NSPLIT, BB), 256>>>();
    kv_reduce<<<(BB * CQ * CO) / 256, 256>>>();
    final_out2<<<dim3(NN / 64, BB), 256>>>(gamma, out);
}

// round 10
// speedup vs baseline: 3.5447x; 1.1721x over previous
#include <cuda_runtime.h>
#include <cuda_bf16.h>
#include <stdint.h>
#include <math.h>

#define BB   4
#define CIN  1024
#define CO   256
#define NN   16384          // H*W
#define NB   (BB*NN)        // 65536
#define CQ   32
#define FN   16384.0f
#define NSPLIT 32

// ---------------- scratch (device globals; no allocations allowed) ----------
__device__ float g_feat[BB*CO*NN];     // RAW conv out (BN applied on the fly)
__device__ float g_Q[BB*CQ*NN];
__device__ float g_K[BB*CQ*NN];
__device__ float g_V[BB*CO*NN];
__device__ float g_scale[CO];
__device__ float g_shift[CO];
__device__ float g_Ksum[BB*CQ];
__device__ float g_Vsum[BB*CO];
__device__ float g_matrix[BB*CQ*CO];            // [b][q][c]
__device__ float g_mpart[NSPLIT*BB*CQ*CO];      // split-n partials

// ---------------- tf32 mma helpers ----------------------------------------
__device__ __forceinline__ unsigned f2tf(float f) {
    unsigned u;
    asm("cvt.rna.tf32.f32 %0, %1;" : "=r"(u) : "f"(f));
    return u;
}
__device__ __forceinline__ void mma_tf32(float* d, const unsigned* a, const unsigned* b) {
    asm("mma.sync.aligned.m16n8k8.row.col.f32.tf32.tf32.f32 "
        "{%0,%1,%2,%3}, {%4,%5,%6,%7}, {%8,%9}, {%0,%1,%2,%3};"
        : "+f"(d[0]), "+f"(d[1]), "+f"(d[2]), "+f"(d[3])
        : "r"(a[0]), "r"(a[1]), "r"(a[2]), "r"(a[3]), "r"(b[0]), "r"(b[1]));
}
__device__ __forceinline__ void cp16(unsigned saddr, const void* gaddr) {
    asm volatile("cp.async.ca.shared.global [%0], [%1], 16;" :: "r"(saddr), "l"(gaddr));
}
__device__ __forceinline__ void cp_commit() {
    asm volatile("cp.async.commit_group;");
}
template<int N> __device__ __forceinline__ void cp_wait() {
    asm volatile("cp.async.wait_group %0;" :: "n"(N));
}

// ===========================================================================
// 1: conv GEMM (tf32) with 4-stage cp.async pipeline.
// Block 128(o) x 128(n), k-step 16. 8 warps 2x4, warp 64(m)x32(n).
// smem stages hold RAW fp32; cvt.rna.tf32 at fragment-load time.
// A layout [o][k] stride 20 (bank map 4g+c4: conflict-free).
// B layout [k][n] stride 136 (bank map 8c4+g: conflict-free).
// ===========================================================================
#define NSTG  4
#define A_STR 20
#define B_STR 136
#define A_WORDS (128*A_STR)              // 2560
#define B_WORDS (16*B_STR)               // 2176
#define STG_WORDS (A_WORDS + B_WORDS)    // 4736
#define CONV_SMEM (NSTG*STG_WORDS*4)     // 75776 bytes

extern __shared__ unsigned dynsm[];

__global__ __launch_bounds__(256, 2) void conv_gemm_ca(
    const float* __restrict__ s5, const float* __restrict__ s4,
    const float* __restrict__ s3, const float* __restrict__ s2,
    const float* __restrict__ w)
{
    const int tid  = threadIdx.x;
    const int lane = tid & 31, warp = tid >> 5;
    const int wm = warp >> 2, wn = warp & 3;       // 2 x 4
    const int g = lane >> 2, c4 = lane & 3;
    const int m0 = blockIdx.x * 128;
    const int o0 = blockIdx.y * 128;
    const int b  = m0 >> 14;
    const int n0 = m0 & (NN - 1);

    uint32_t sbase;
    asm("{.reg .u64 t; cvta.to.shared.u64 t, %1; cvt.u32.u64 %0, t;}"
        : "=r"(sbase) : "l"(dynsm));

    // copy mappings
    const int ao = tid >> 1, akq = (tid & 1) * 8;   // A: row ao, k akq..akq+7
    const int bk = tid >> 4, bnf = (tid & 15) * 8;  // B: row bk, n bnf..bnf+7
    const float* ag_base = &w[(o0 + ao) * CIN + akq];
    const uint32_t sa = sbase + (ao * A_STR + akq) * 4;
    const uint32_t sb = sbase + (A_WORDS + bk * B_STR + bnf) * 4;

    // issue one stage's copies (stage st holds k-tile k0 = kt*16)
    auto issue = [&](int st, int kt) {
        const int k0 = kt * 16;
        const uint32_t so = st * (STG_WORDS * 4);
        const float* ag = ag_base + k0;
        cp16(sa + so,      ag);
        cp16(sa + so + 16, ag + 4);
        const float* src = (k0 < 256) ? s5 : (k0 < 512) ? s4 : (k0 < 768) ? s3 : s2;
        const float* bg = &src[((b << 8) + (k0 & 255) + bk) * NN + n0 + bnf];
        cp16(sb + so,      bg);
        cp16(sb + so + 16, bg + 4);
        cp_commit();
    };

    issue(0, 0); issue(1, 1); issue(2, 2);

    float acc[4][4][4] = {};
    for (int t = 0; t < 64; t++) {
        cp_wait<NSTG - 2>();
        __syncthreads();
        if (t + NSTG - 1 < 64) issue((t + NSTG - 1) & (NSTG - 1), t + NSTG - 1);

        const unsigned* A0 = dynsm + (t & (NSTG - 1)) * STG_WORDS;
        const unsigned* B0 = A0 + A_WORDS;
        #pragma unroll
        for (int ks = 0; ks < 16; ks += 8) {
            unsigned af[4][4], bf[4][2];
            #pragma unroll
            for (int mi = 0; mi < 4; mi++) {
                int m = wm * 64 + mi * 16 + g;
                af[mi][0] = f2tf(__uint_as_float(A0[ m      * A_STR + ks + c4]));
                af[mi][1] = f2tf(__uint_as_float(A0[(m + 8) * A_STR + ks + c4]));
                af[mi][2] = f2tf(__uint_as_float(A0[ m      * A_STR + ks + c4 + 4]));
                af[mi][3] = f2tf(__uint_as_float(A0[(m + 8) * A_STR + ks + c4 + 4]));
            }
            #pragma unroll
            for (int nj = 0; nj < 4; nj++) {
                int n = wn * 32 + nj * 8 + g;
                bf[nj][0] = f2tf(__uint_as_float(B0[(ks + c4)     * B_STR + n]));
                bf[nj][1] = f2tf(__uint_as_float(B0[(ks + c4 + 4) * B_STR + n]));
            }
            #pragma unroll
            for (int mi = 0; mi < 4; mi++)
                #pragma unroll
                for (int nj = 0; nj < 4; nj++)
                    mma_tf32(acc[mi][nj], af[mi], bf[nj]);
        }
    }
    #pragma unroll
    for (int mi = 0; mi < 4; mi++) {
        int o1 = o0 + wm * 64 + mi * 16 + g;
        #pragma unroll
        for (int nj = 0; nj < 4; nj++) {
            int nn1 = n0 + wn * 32 + nj * 8 + c4 * 2;
            float* base = &g_feat[(b * CO + o1) * NN + nn1];
            *(float2*)base            = make_float2(acc[mi][nj][0], acc[mi][nj][1]);
            *(float2*)(base + 8 * NN) = make_float2(acc[mi][nj][2], acc[mi][nj][3]);
        }
    }
}

// ---------------- 2: per-channel BN stats -> scale/shift -------------------
__global__ __launch_bounds__(256) void bn_stats(
    const float* __restrict__ bn_gamma, const float* __restrict__ bn_beta)
{
    const int o = blockIdx.x;
    const int t = threadIdx.x;
    float s = 0.f, ss = 0.f;
    for (int b = 0; b < BB; b++) {
        const float* p = g_feat + (b * CO + o) * NN;
        for (int n = t; n < NN; n += 256) { float v = p[n]; s += v; ss += v * v; }
    }
    __shared__ float sh[256], sh2[256];
    sh[t] = s; sh2[t] = ss; __syncthreads();
    for (int st = 128; st > 0; st >>= 1) {
        if (t < st) { sh[t] += sh[t + st]; sh2[t] += sh2[t + st]; }
        __syncthreads();
    }
    if (t == 0) {
        const float inv = 1.0f / (float)(BB * NN);
        float mean = sh[0] * inv;
        float var  = sh2[0] * inv - mean * mean;
        float sc   = bn_gamma[o] * rsqrtf(var + 1e-5f);
        g_scale[o] = sc;
        g_shift[o] = bn_beta[o] - mean * sc;
    }
}

// ===========================================================================
// 3: fused QKV GEMM (tf32), BN+ReLU applied to feat inline while staging B.
// Block 64(r) x 256(n), k-step 16, double-buffered. 8 warps 2x4, warp 32x64.
// ===========================================================================
#define QASTR 72    // 72 % 32 == 8
#define QBSTR 264   // 264 % 32 == 8
__device__ __forceinline__ float* qkv_dst(int r, int b,
    const float* bq, const float* bk, const float* bv, float& bias)
{
    if (r < 32) { bias = bq[r];      return &g_Q[(b * CQ + r) * NN]; }
    if (r < 64) { bias = bk[r - 32]; return &g_K[(b * CQ + r - 32) * NN]; }
    bias = bv[r - 64];               return &g_V[(b * CO + r - 64) * NN];
}

__global__ __launch_bounds__(256, 2) void qkv_gemm_tf32(
    const float* __restrict__ wq, const float* __restrict__ bq,
    const float* __restrict__ wk, const float* __restrict__ bk,
    const float* __restrict__ wv, const float* __restrict__ bv)
{
    __shared__ unsigned As[2][16*QASTR];
    __shared__ unsigned Bs[2][16*QBSTR];
    const int tid  = threadIdx.x;
    const int lane = tid & 31, warp = tid >> 5;
    const int wm = warp >> 2, wn = warp & 3;     // 2 x 4 warps, warp 32m x 64n
    const int g = lane >> 2, c4 = lane & 3;
    const int m0 = blockIdx.x * 256;
    const int r0 = blockIdx.y * 64;              // 0..256 step 64 (5 blocks)
    const int b  = m0 >> 14;
    const int n0 = m0 & (NN - 1);

    const int ao = tid & 63,  ak = (tid >> 6) * 4;    // A: col ao, k ak..ak+3
    const int bkr = tid >> 4, bnf = (tid & 15) * 16;  // B: row bkr, n bnf..bnf+15

    const int ar = r0 + ao;
    const float* wrow = (ar < 32) ? (wq + ar * CO)
                      : (ar < 64) ? (wk + (ar - 32) * CO)
                                  : (wv + (ar - 64) * CO);

    float4 pa, pb[4]; float psc, psh;
    {
        pa = *(const float4*)&wrow[ak];
        psc = g_scale[bkr]; psh = g_shift[bkr];
        const float* br = &g_feat[(b * CO + bkr) * NN + n0 + bnf];
        #pragma unroll
        for (int j = 0; j < 4; j++) pb[j] = *(const float4*)(br + j * 4);
    }
    {
        As[0][(ak+0)*QASTR+ao]=f2tf(pa.x); As[0][(ak+1)*QASTR+ao]=f2tf(pa.y);
        As[0][(ak+2)*QASTR+ao]=f2tf(pa.z); As[0][(ak+3)*QASTR+ao]=f2tf(pa.w);
        unsigned* d = &Bs[0][bkr*QBSTR+bnf];
        #pragma unroll
        for (int j = 0; j < 4; j++) {
            d[j*4+0]=f2tf(fmaxf(fmaf(pb[j].x,psc,psh),0.f));
            d[j*4+1]=f2tf(fmaxf(fmaf(pb[j].y,psc,psh),0.f));
            d[j*4+2]=f2tf(fmaxf(fmaf(pb[j].z,psc,psh),0.f));
            d[j*4+3]=f2tf(fmaxf(fmaf(pb[j].w,psc,psh),0.f));
        }
    }
    __syncthreads();

    float acc[2][8][4] = {};
    for (int t = 0; t < 16; t++) {
        const int buf = t & 1;
        if (t < 15) {
            const int k0 = (t + 1) * 16;
            pa = *(const float4*)&wrow[k0 + ak];
            psc = g_scale[k0 + bkr]; psh = g_shift[k0 + bkr];
            const float* br = &g_feat[(b * CO + k0 + bkr) * NN + n0 + bnf];
            #pragma unroll
            for (int j = 0; j < 4; j++) pb[j] = *(const float4*)(br + j * 4);
        }
        #pragma unroll
        for (int ks = 0; ks < 16; ks += 8) {
            unsigned af[2][4], bf[8][2];
            #pragma unroll
            for (int mi = 0; mi < 2; mi++) {
                int m = wm * 32 + mi * 16 + g;
                af[mi][0] = As[buf][(ks+c4  )*QASTR + m];
                af[mi][1] = As[buf][(ks+c4  )*QASTR + m + 8];
                af[mi][2] = As[buf][(ks+c4+4)*QASTR + m];
                af[mi][3] = As[buf][(ks+c4+4)*QASTR + m + 8];
            }
            #pragma unroll
            for (int nj = 0; nj < 8; nj++) {
                int n = wn * 64 + nj * 8 + g;
                bf[nj][0] = Bs[buf][(ks+c4  )*QBSTR + n];
                bf[nj][1] = Bs[buf][(ks+c4+4)*QBSTR + n];
            }
            #pragma unroll
            for (int mi = 0; mi < 2; mi++)
                #pragma unroll
                for (int nj = 0; nj < 8; nj++)
                    mma_tf32(acc[mi][nj], af[mi], bf[nj]);
        }
        if (t < 15) {
            const int nb = buf ^ 1;
            As[nb][(ak+0)*QASTR+ao]=f2tf(pa.x); As[nb][(ak+1)*QASTR+ao]=f2tf(pa.y);
            As[nb][(ak+2)*QASTR+ao]=f2tf(pa.z); As[nb][(ak+3)*QASTR+ao]=f2tf(pa.w);
            unsigned* d = &Bs[nb][bkr*QBSTR+bnf];
            #pragma unroll
            for (int j = 0; j < 4; j++) {
                d[j*4+0]=f2tf(fmaxf(fmaf(pb[j].x,psc,psh),0.f));
                d[j*4+1]=f2tf(fmaxf(fmaf(pb[j].y,psc,psh),0.f));
                d[j*4+2]=f2tf(fmaxf(fmaf(pb[j].z,psc,psh),0.f));
                d[j*4+3]=f2tf(fmaxf(fmaf(pb[j].w,psc,psh),0.f));
            }
            __syncthreads();
        }
    }
    #pragma unroll
    for (int mi = 0; mi < 2; mi++) {
        int r1 = r0 + wm * 32 + mi * 16 + g;
        float bias1, bias2;
        float* d1 = qkv_dst(r1,     b, bq, bk, bv, bias1);
        float* d2 = qkv_dst(r1 + 8, b, bq, bk, bv, bias2);
        #pragma unroll
        for (int nj = 0; nj < 8; nj++) {
            int nn1 = n0 + wn * 64 + nj * 8 + c4 * 2;
            *(float2*)&d1[nn1] = make_float2(acc[mi][nj][0] + bias1, acc[mi][nj][1] + bias1);
            *(float2*)&d2[nn1] = make_float2(acc[mi][nj][2] + bias2, acc[mi][nj][3] + bias2);
        }
    }
}

// ---------------- 4: L2-normalize Q and K over channel dim -----------------
__global__ __launch_bounds__(256) void l2norm_qk()
{
    int col = blockIdx.x * 256 + threadIdx.x;
    int b = col >> 14, n = col & (NN - 1);
    {
        float* p = g_Q + b * CQ * NN + n;
        float v[CQ]; float s = 0.f;
        #pragma unroll
        for (int q = 0; q < CQ; q++) { v[q] = p[q * NN]; s += v[q] * v[q]; }
        float r = 1.f / fmaxf(sqrtf(s), 1e-6f);
        #pragma unroll
        for (int q = 0; q < CQ; q++) p[q * NN] = v[q] * r;
    }
    {
        float* p = g_K + b * CQ * NN + n;
        float v[CQ]; float s = 0.f;
        #pragma unroll
        for (int q = 0; q < CQ; q++) { v[q] = p[q * NN]; s += v[q] * v[q]; }
        float r = 1.f / fmaxf(sqrtf(s), 1e-6f);
        #pragma unroll
        for (int q = 0; q < CQ; q++) p[q * NN] = v[q] * r;
    }
}

// ---------------- 5: row sums: Ksum[b,q], Vsum[b,c] ------------------------
__global__ __launch_bounds__(256) void row_sums()
{
    const int id = blockIdx.x;
    const int b = id / (CQ + CO);
    const int r = id % (CQ + CO);
    const float* p; float* dst;
    if (r < CQ) { p = g_K + (b * CQ + r) * NN;        dst = &g_Ksum[b * CQ + r]; }
    else        { p = g_V + (b * CO + (r - CQ)) * NN; dst = &g_Vsum[b * CO + r - CQ]; }
    const int t = threadIdx.x;
    float s = 0.f;
    for (int n = t; n < NN; n += 256) s += p[n];
    __shared__ float sh[256];
    sh[t] = s; __syncthreads();
    for (int st = 128; st > 0; st >>= 1) {
        if (t < st) sh[t] += sh[t + st];
        __syncthreads();
    }
    if (t == 0) *dst = sh[0];
}

// ---------------- 6a: split-n KV GEMM (tf32): part[ns,b,q,c] ---------------
#define KSTR 36
__global__ __launch_bounds__(256) void kv_partial()
{
    const int ns = blockIdx.x;
    const int b  = blockIdx.y;
    const int n_start = ns * (NN / NSPLIT);
    __shared__ unsigned Ks[32*KSTR];
    __shared__ unsigned Vs[256*KSTR];
    const int t = threadIdx.x;
    const int lane = t & 31, warp = t >> 5;
    const int g = lane >> 2, c4 = lane & 3;

    float acc[2][4][4] = {};
    for (int ch = 0; ch < NN / NSPLIT; ch += 32) {
        const int n0c = n_start + ch;
        {
            int row = t >> 3, f = t & 7;
            float4 v = *(const float4*)&g_K[(b * CQ + row) * NN + n0c + f * 4];
            unsigned* d = &Ks[row * KSTR + f * 4];
            d[0] = f2tf(v.x); d[1] = f2tf(v.y); d[2] = f2tf(v.z); d[3] = f2tf(v.w);
        }
        #pragma unroll
        for (int l = 0; l < 8; l++) {
            int idx = t + l * 256;
            int row = idx >> 3, f = idx & 7;
            float4 v = *(const float4*)&g_V[(b * CO + row) * NN + n0c + f * 4];
            unsigned* d = &Vs[row * KSTR + f * 4];
            d[0] = f2tf(v.x); d[1] = f2tf(v.y); d[2] = f2tf(v.z); d[3] = f2tf(v.w);
        }
        __syncthreads();
        #pragma unroll
        for (int ks = 0; ks < 32; ks += 8) {
            unsigned af[2][4], bf[4][2];
            #pragma unroll
            for (int mi = 0; mi < 2; mi++) {
                int r = mi * 16 + g;
                af[mi][0] = Ks[ r      * KSTR + ks + c4];
                af[mi][1] = Ks[(r + 8) * KSTR + ks + c4];
                af[mi][2] = Ks[ r      * KSTR + ks + c4 + 4];
                af[mi][3] = Ks[(r + 8) * KSTR + ks + c4 + 4];
            }
            #pragma unroll
            for (int nj = 0; nj < 4; nj++) {
                int c = warp * 32 + nj * 8 + g;
                bf[nj][0] = Vs[c * KSTR + ks + c4];
                bf[nj][1] = Vs[c * KSTR + ks + c4 + 4];
            }
            #pragma unroll
            for (int mi = 0; mi < 2; mi++)
                #pragma unroll
                for (int nj = 0; nj < 4; nj++)
                    mma_tf32(acc[mi][nj], af[mi], bf[nj]);
        }
        __syncthreads();
    }
    const int pbase = (ns * BB + b) * CQ * CO;
    #pragma unroll
    for (int mi = 0; mi < 2; mi++) {
        int q = mi * 16 + g;
        #pragma unroll
        for (int nj = 0; nj < 4; nj++) {
            int c = warp * 32 + nj * 8 + c4 * 2;
            *(float2*)&g_mpart[pbase + q * CO + c]       = make_float2(acc[mi][nj][0], acc[mi][nj][1]);
            *(float2*)&g_mpart[pbase + (q + 8) * CO + c] = make_float2(acc[mi][nj][2], acc[mi][nj][3]);
        }
    }
}

// ---------------- 6b: reduce partials -> g_matrix --------------------------
__global__ __launch_bounds__(256) void kv_reduce()
{
    int idx = blockIdx.x * 256 + threadIdx.x;
    float s = 0.f;
    #pragma unroll
    for (int ns = 0; ns < NSPLIT; ns++) s += g_mpart[ns * (BB * CQ * CO) + idx];
    g_matrix[idx] = s;
}

// ---------------- 7: final: out = featBN + nan2num(gamma*(Vsum+Qn.M)*tail) -
__global__ __launch_bounds__(256) void final_out2(
    const float* __restrict__ gamma_p, float* __restrict__ out)
{
    const int b  = blockIdx.y;
    const int n0 = blockIdx.x * 64;
    __shared__ float qsh[CQ * 64];       // [q][n]
    __shared__ float msh[CO * 33];       // [c][q] stride 33
    __shared__ float vsum_sh[CO], ksum_sh[CQ];
    __shared__ float tail[64];
    const int t = threadIdx.x;

    #pragma unroll
    for (int l = 0; l < 2; l++) {
        int idx = t + l * 256;
        int q = idx >> 4, nf = (idx & 15) * 4;
        *(float4*)&qsh[q * 64 + nf] = *(const float4*)&g_Q[(b * CQ + q) * NN + n0 + nf];
    }
    #pragma unroll
    for (int l = 0; l < 32; l++) {
        int idx = t + l * 256;           // idx = q*CO + c
        int q = idx >> 8, c = idx & 255;
        msh[c * 33 + q] = g_matrix[b * CQ * CO + idx];
    }
    if (t < CO) vsum_sh[t] = g_Vsum[b * CO + t];
    if (t < CQ) ksum_sh[t] = g_Ksum[b * CQ + t];
    __syncthreads();
    if (t < 64) {
        float e = 0.f;
        #pragma unroll
        for (int q = 0; q < CQ; q++) e += qsh[q * 64 + t] * ksum_sh[q];
        tail[t] = 1.f / fmaxf(FN + e, 1e-6f);
    }
    __syncthreads();

    const int tc = t >> 3, tn = t & 7;   // 8c x 8n per thread
    float acc[8][8] = {};
    #pragma unroll 4
    for (int q = 0; q < CQ; q++) {
        float4 qa = *(const float4*)&qsh[q * 64 + tn * 8];
        float4 qb = *(const float4*)&qsh[q * 64 + tn * 8 + 4];
        float qv[8] = {qa.x, qa.y, qa.z, qa.w, qb.x, qb.y, qb.z, qb.w};
        #pragma unroll
        for (int cc = 0; cc < 8; cc++) {
            float mv = msh[(tc * 8 + cc) * 33 + q];
            #pragma unroll
            for (int nn = 0; nn < 8; nn++) acc[cc][nn] += mv * qv[nn];
        }
    }
    const float gam = gamma_p[0];
    #pragma unroll
    for (int cc = 0; cc < 8; cc++) {
        int c = tc * 8 + cc;
        float vs = vsum_sh[c];
        float sc = g_scale[c], sh = g_shift[c];
        int base = (b * CO + c) * NN + n0 + tn * 8;
        float4 f1 = *(const float4*)&g_feat[base];
        float4 f2 = *(const float4*)&g_feat[base + 4];
        float fr[8] = {
            fmaxf(fmaf(f1.x,sc,sh),0.f), fmaxf(fmaf(f1.y,sc,sh),0.f),
            fmaxf(fmaf(f1.z,sc,sh),0.f), fmaxf(fmaf(f1.w,sc,sh),0.f),
            fmaxf(fmaf(f2.x,sc,sh),0.f), fmaxf(fmaf(f2.y,sc,sh),0.f),
            fmaxf(fmaf(f2.z,sc,sh),0.f), fmaxf(fmaf(f2.w,sc,sh),0.f)};
        float r[8];
        #pragma unroll
        for (int nn = 0; nn < 8; nn++) {
            float v = gam * (vs + acc[cc][nn]) * tail[tn * 8 + nn];
            if (isnan(v)) v = 0.f;
            else if (isinf(v)) v = (v > 0.f) ? 1.f : -1.f;
            r[nn] = v + fr[nn];
        }
        *(float4*)&out[base]     = make_float4(r[0], r[1], r[2], r[3]);
        *(float4*)&out[base + 4] = make_float4(r[4], r[5], r[6], r[7]);
    }
}

// ---------------------------------------------------------------------------
extern "C" void kernel_launch(void* const* d_in, const int* in_sizes, int n_in,
                              void* d_out, int out_size)
{
    const float* s5       = (const float*)d_in[0];
    const float* s4       = (const float*)d_in[1];
    const float* s3       = (const float*)d_in[2];
    const float* s2       = (const float*)d_in[3];
    const float* w_conv   = (const float*)d_in[4];
    const float* bn_gamma = (const float*)d_in[5];
    const float* bn_beta  = (const float*)d_in[6];
    const float* wq       = (const float*)d_in[7];
    const float* bq       = (const float*)d_in[8];
    const float* wk       = (const float*)d_in[9];
    const float* bk       = (const float*)d_in[10];
    const float* wv       = (const float*)d_in[11];
    const float* bv       = (const float*)d_in[12];
    const float* gamma    = (const float*)d_in[13];
    float* out = (float*)d_out;

    // idempotent, host-side, call every time (no static call-count guards)
    cudaFuncSetAttribute(conv_gemm_ca,
                         cudaFuncAttributeMaxDynamicSharedMemorySize, CONV_SMEM);

    conv_gemm_ca<<<dim3(NB / 128, CO / 128), 256, CONV_SMEM>>>(s5, s4, s3, s2, w_conv);
    bn_stats<<<CO, 256>>>(bn_gamma, bn_beta);
    qkv_gemm_tf32<<<dim3(NB / 256, 5), 256>>>(wq, bq, wk, bk, wv, bv);
    l2norm_qk<<<NB / 256, 256>>>();
    row_sums<<<BB * (CQ + CO), 256>>>();
    kv_partial<<<dim3(NSPLIT, BB), 256>>>();
    kv_reduce<<<(BB * CQ * CO) / 256, 256>>>();
    final_out2<<<dim3(NN / 64, BB), 256>>>(gamma, out);
}